// round 1
// baseline (speedup 1.0000x reference)
#include <cuda_runtime.h>

#define NN      131072
#define KK      27
#define C       32
#define NKTOT   (NN * KK)          // 3538944 scatter entries
#define CAP     96                 // bucket capacity (Poisson(27), P(overflow) ~ 2.5e-10)
#define BN_BLKS 1024
#define EPS_F   1e-5f

// -------- device scratch (static: allocation at module load, allowed) --------
__device__ float g_contrib[(size_t)NKTOT * C];   // 453 MB: contrib[n][k][o]
__device__ int   g_fill[NN];
__device__ int   g_list[(size_t)NN * CAP];       // 50 MB inverse index
__device__ float g_part[BN_BLKS * 64];           // per-block BN partials (sum, sumsq)
__device__ float g_stats[64];                    // [0:32) scale, [32:64) shift

// -------- 1. zero fill counters --------
__global__ void k_zero() {
    int i = blockIdx.x * blockDim.x + threadIdx.x;
    if (i < NN) g_fill[i] = 0;
}

// -------- 2. build inverse index: bucket m <- entry e = n*27+k --------
__global__ void k_fill(const int* __restrict__ neigh) {
    int e = blockIdx.x * blockDim.x + threadIdx.x;
    if (e >= NKTOT) return;
    int m   = neigh[e];
    int pos = atomicAdd(&g_fill[m], 1);
    if (pos < CAP) g_list[(size_t)m * CAP + pos] = e;
}

// -------- 3. GEMM: contrib[n][k][o] = sum_i data[n][i] * W[k][i][o] --------
// grid (512 node-tiles, 27 taps), 256 threads.
// Per block: 256 nodes x 32 cols, one tap. W[k] (4KB) + transposed data tile
// (32x257 padded, conflict-free) in smem. Thread = 8 nodes x 4 cols (32 acc).
// Lane mapping: o4 = lane&7 (col group, W read = 128B dense LDS.128),
// lane>>3 = node sub (data read = 16B broadcast-4). Epilogue: direct STG.128,
// warp instr = 4 nodes x 128B contiguous segments (100% sectors).
__global__ __launch_bounds__(256) void k_gemm(const float* __restrict__ data,
                                              const float* __restrict__ weight) {
    __shared__ float sW[C][C];
    __shared__ float sD[C][257];
    const int k    = blockIdx.y;
    const int tile = blockIdx.x;
    const int tid  = threadIdx.x;

    // load W[k]: 1024 floats = 256 float4
    reinterpret_cast<float4*>(sW)[tid] =
        reinterpret_cast<const float4*>(weight + k * C * C)[tid];

    // load data tile [256 nodes][32 ch], transpose into sD[i][node]
    const float4* src = reinterpret_cast<const float4*>(data + (size_t)tile * 256 * C);
#pragma unroll
    for (int jj = 0; jj < 8; ++jj) {
        int    idx  = tid + 256 * jj;       // coalesced float4 stream
        float4 v    = src[idx];
        int    node = idx >> 3;
        int    i4   = (idx & 7) * 4;
        sD[i4 + 0][node] = v.x;
        sD[i4 + 1][node] = v.y;
        sD[i4 + 2][node] = v.z;
        sD[i4 + 3][node] = v.w;
    }
    __syncthreads();

    const int lane    = tid & 31;
    const int warp    = tid >> 5;
    const int c0      = (lane & 7) * 4;
    const int nodeoff = warp * 32 + (lane >> 3);

    float acc[8][4];
#pragma unroll
    for (int j = 0; j < 8; ++j)
#pragma unroll
        for (int q = 0; q < 4; ++q) acc[j][q] = 0.f;

#pragma unroll
    for (int i = 0; i < C; ++i) {
        const float4 w = *reinterpret_cast<const float4*>(&sW[i][c0]);
#pragma unroll
        for (int j = 0; j < 8; ++j) {
            float d = sD[i][nodeoff + 4 * j];
            acc[j][0] += d * w.x;
            acc[j][1] += d * w.y;
            acc[j][2] += d * w.z;
            acc[j][3] += d * w.w;
        }
    }

#pragma unroll
    for (int j = 0; j < 8; ++j) {
        size_t n = (size_t)tile * 256 + nodeoff + 4 * j;
        float4* dst = reinterpret_cast<float4*>(g_contrib + ((n * KK + k) * C + c0));
        *dst = make_float4(acc[j][0], acc[j][1], acc[j][2], acc[j][3]);
    }
}

// -------- 4. gather: out[m][o] = sum over bucket entries of contrib[e][o] ---
// one warp per output node; lane = channel; 128B-row reads, MLP-4 unroll.
__global__ __launch_bounds__(256) void k_gather(float* __restrict__ out) {
    int m = (blockIdx.x * blockDim.x + threadIdx.x) >> 5;
    if (m >= NN) return;
    int lane = threadIdx.x & 31;
    int cnt  = g_fill[m];
    if (cnt > CAP) cnt = CAP;
    const int* lst = g_list + (size_t)m * CAP;
    float acc = 0.f;
    int j = 0;
    for (; j + 4 <= cnt; j += 4) {
        int e0 = lst[j], e1 = lst[j + 1], e2 = lst[j + 2], e3 = lst[j + 3];
        float v0 = g_contrib[(size_t)e0 * C + lane];
        float v1 = g_contrib[(size_t)e1 * C + lane];
        float v2 = g_contrib[(size_t)e2 * C + lane];
        float v3 = g_contrib[(size_t)e3 * C + lane];
        acc += ((v0 + v1) + (v2 + v3));
    }
    for (; j < cnt; ++j)
        acc += g_contrib[(size_t)lst[j] * C + lane];
    out[(size_t)m * C + lane] = acc;
}

// -------- 5. BN stats, stage 1: deterministic per-block partials ------------
__global__ __launch_bounds__(256) void k_bnpart(const float* __restrict__ out) {
    __shared__ float ss[8][32], sq[8][32];
    int ch = threadIdx.x & 31, w = threadIdx.x >> 5;
    int r0 = blockIdx.x * (NN / BN_BLKS);           // 128 rows per block
    float s = 0.f, q = 0.f;
    for (int r = r0 + w; r < r0 + (NN / BN_BLKS); r += 8) {
        float v = out[(size_t)r * C + ch];
        s += v;
        q += v * v;
    }
    ss[w][ch] = s;
    sq[w][ch] = q;
    __syncthreads();
    if (w == 0) {
        float S = 0.f, Q = 0.f;
#pragma unroll
        for (int t = 0; t < 8; ++t) { S += ss[t][ch]; Q += sq[t][ch]; }
        g_part[blockIdx.x * 64 + ch]      = S;
        g_part[blockIdx.x * 64 + 32 + ch] = Q;
    }
}

// -------- 6. BN stats, stage 2: final mean/var -> fused scale/shift ---------
__global__ __launch_bounds__(256) void k_bnfinal(const float* __restrict__ gamma,
                                                 const float* __restrict__ beta) {
    __shared__ float ss[8][32], sq[8][32];
    int ch = threadIdx.x & 31, w = threadIdx.x >> 5;
    float S = 0.f, Q = 0.f;
    for (int b = w; b < BN_BLKS; b += 8) {
        S += g_part[b * 64 + ch];
        Q += g_part[b * 64 + 32 + ch];
    }
    ss[w][ch] = S;
    sq[w][ch] = Q;
    __syncthreads();
    if (w == 0) {
        float St = 0.f, Qt = 0.f;
#pragma unroll
        for (int t = 0; t < 8; ++t) { St += ss[t][ch]; Qt += sq[t][ch]; }
        float mean  = St * (1.0f / NN);
        float var   = Qt * (1.0f / NN) - mean * mean;
        float rstd  = rsqrtf(var + EPS_F);
        float scale = gamma[ch] * rstd;
        g_stats[ch]      = scale;
        g_stats[32 + ch] = beta[ch] - mean * scale;
    }
}

// -------- 7. apply BN + ReLU in place --------
__global__ __launch_bounds__(256) void k_apply(float* __restrict__ out) {
    int i = blockIdx.x * blockDim.x + threadIdx.x;
    if (i >= NN * C) return;
    int   ch = i & 31;
    float y  = fmaf(out[i], g_stats[ch], g_stats[32 + ch]);
    out[i] = fmaxf(y, 0.f);
}

extern "C" void kernel_launch(void* const* d_in, const int* in_sizes, int n_in,
                              void* d_out, int out_size) {
    const float* data   = (const float*)d_in[0];   // [N, 32]
    const float* weight = (const float*)d_in[1];   // [27, 32, 32]
    const float* gamma  = (const float*)d_in[2];   // [32]
    const float* beta   = (const float*)d_in[3];   // [32]
    const int*   neigh  = (const int*)d_in[4];     // [N, 27]
    float*       out    = (float*)d_out;           // [N, 32]

    k_zero<<<(NN + 255) / 256, 256>>>();
    k_fill<<<(NKTOT + 255) / 256, 256>>>(neigh);
    k_gemm<<<dim3(NN / 256, KK), 256>>>(data, weight);
    k_gather<<<(NN * 32 + 255) / 256, 256>>>(out);
    k_bnpart<<<BN_BLKS, 256>>>(out);
    k_bnfinal<<<1, 256>>>(gamma, beta);
    k_apply<<<(NN * C + 255) / 256, 256>>>(out);
}

// round 2
// speedup vs baseline: 1.1637x; 1.1637x over previous
#include <cuda_runtime.h>
#include <cuda_fp16.h>

#define NN      131072
#define KK      27
#define C       32
#define NKTOT   (NN * KK)          // 3538944 scatter entries
#define CAP     96                 // bucket capacity (Poisson(27), P(overflow) ~ 2.5e-10)
#define BN_BLKS 1024
#define EPS_F   1e-5f

// -------- device scratch --------
__device__ __half g_contrib16[(size_t)NKTOT * C];  // 226 MB: contrib[n][k][o] fp16
__device__ int    g_fill[NN];
__device__ int    g_list[(size_t)NN * CAP];        // 50 MB inverse index
__device__ float  g_part[BN_BLKS * 64];            // per-block BN partials (sum, sumsq)
__device__ float  g_stats[64];                     // [0:32) scale, [32:64) shift

// -------- 1. zero fill counters --------
__global__ void k_zero() {
    int i = blockIdx.x * blockDim.x + threadIdx.x;
    if (i < NN) g_fill[i] = 0;
}

// -------- 2. build inverse index: bucket m <- entry e = n*27+k --------
__global__ void k_fill(const int* __restrict__ neigh) {
    int t = blockIdx.x * blockDim.x + threadIdx.x;      // t < NKTOT/4
    if (t >= NKTOT / 4) return;
    int4 m4 = reinterpret_cast<const int4*>(neigh)[t];
    int e0 = t * 4;
#pragma unroll
    for (int q = 0; q < 4; ++q) {
        int m   = (q == 0) ? m4.x : (q == 1) ? m4.y : (q == 2) ? m4.z : m4.w;
        int pos = atomicAdd(&g_fill[m], 1);
        if (pos < CAP) g_list[(size_t)m * CAP + pos] = e0 + q;
    }
}

// -------- 3. GEMM: contrib[n][k][o] = sum_i data[n][i] * W[k][i][o] --------
// grid (512 node-tiles, 3 k-groups), 256 threads. Each block: 256 nodes, 9 taps.
// Data tile transposed into smem once; per tap: W[k] smem load, FFMA2 (packed
// f32x2) mainloop = 2x fp32 FMA rate, fp16 epilogue (STG.64 per thread).
__global__ __launch_bounds__(256) void k_gemm(const float* __restrict__ data,
                                              const float* __restrict__ weight) {
    __shared__ float sW[C][C];
    __shared__ float sD[C][257];
    const int tile  = blockIdx.x;
    const int kbase = blockIdx.y * 9;
    const int tid   = threadIdx.x;

    // load data tile [256 nodes][32 ch], transpose into sD[i][node]
    const float4* src = reinterpret_cast<const float4*>(data + (size_t)tile * 256 * C);
#pragma unroll
    for (int jj = 0; jj < 8; ++jj) {
        int    idx  = tid + 256 * jj;       // coalesced float4 stream
        float4 v    = src[idx];
        int    node = idx >> 3;
        int    i4   = (idx & 7) * 4;
        sD[i4 + 0][node] = v.x;
        sD[i4 + 1][node] = v.y;
        sD[i4 + 2][node] = v.z;
        sD[i4 + 3][node] = v.w;
    }

    const int lane    = tid & 31;
    const int warp    = tid >> 5;
    const int c0      = (lane & 7) * 4;
    const int nodeoff = warp * 32 + (lane >> 3);

    for (int kt = 0; kt < 9; ++kt) {
        const int k = kbase + kt;
        __syncthreads();                    // sD ready (iter 0) / sW free (iter >0)
        reinterpret_cast<float4*>(sW)[tid] =
            reinterpret_cast<const float4*>(weight + k * C * C)[tid];
        __syncthreads();

        unsigned long long acc[8][2];
#pragma unroll
        for (int j = 0; j < 8; ++j) { acc[j][0] = 0ull; acc[j][1] = 0ull; }

#pragma unroll
        for (int i = 0; i < C; ++i) {
            const float4 w = *reinterpret_cast<const float4*>(&sW[i][c0]);
            unsigned long long w01, w23;
            asm("mov.b64 %0, {%1, %2};" : "=l"(w01) : "f"(w.x), "f"(w.y));
            asm("mov.b64 %0, {%1, %2};" : "=l"(w23) : "f"(w.z), "f"(w.w));
#pragma unroll
            for (int j = 0; j < 8; ++j) {
                float d = sD[i][nodeoff + 4 * j];
                unsigned long long dd;
                asm("mov.b64 %0, {%1, %1};" : "=l"(dd) : "f"(d));
                asm("fma.rn.f32x2 %0, %1, %2, %0;" : "+l"(acc[j][0]) : "l"(dd), "l"(w01));
                asm("fma.rn.f32x2 %0, %1, %2, %0;" : "+l"(acc[j][1]) : "l"(dd), "l"(w23));
            }
        }

        // epilogue: fp32 pairs -> half2, one STG.64 per thread per node
#pragma unroll
        for (int j = 0; j < 8; ++j) {
            float a0, a1, a2, a3;
            asm("mov.b64 {%0, %1}, %2;" : "=f"(a0), "=f"(a1) : "l"(acc[j][0]));
            asm("mov.b64 {%0, %1}, %2;" : "=f"(a2), "=f"(a3) : "l"(acc[j][1]));
            __half2 h01 = __floats2half2_rn(a0, a1);
            __half2 h23 = __floats2half2_rn(a2, a3);
            size_t  n   = (size_t)tile * 256 + nodeoff + 4 * j;
            uint2   u;
            u.x = *reinterpret_cast<unsigned*>(&h01);
            u.y = *reinterpret_cast<unsigned*>(&h23);
            *reinterpret_cast<uint2*>(g_contrib16 + ((n * KK + k) * C + c0)) = u;
        }
    }
}

// -------- 4. gather: out[m][o] = sum over bucket entries of contrib16[e][o] --
// one warp per output node; 2 entries per warp-load (lanes 0-15 entry A,
// lanes 16-31 entry B, half2 per lane) -> full 128B requests, MLP-8.
__global__ __launch_bounds__(256) void k_gather(float* __restrict__ out) {
    int m = (blockIdx.x * blockDim.x + threadIdx.x) >> 5;
    if (m >= NN) return;
    const int lane = threadIdx.x & 31;
    const int hsel = lane >> 4;          // which entry of the pair
    const int ch2  = lane & 15;          // half2 column
    int cnt = g_fill[m];
    if (cnt > CAP) cnt = CAP;
    const int* lst = g_list + (size_t)m * CAP;

    float2 acc = make_float2(0.f, 0.f);
    int j = 0;
    for (; j + 8 <= cnt; j += 8) {
#pragma unroll
        for (int t = 0; t < 4; ++t) {
            int     e = lst[j + 2 * t + hsel];
            __half2 v = *reinterpret_cast<const __half2*>(
                            g_contrib16 + (size_t)e * C + ch2 * 2);
            float2  f = __half22float2(v);
            acc.x += f.x;
            acc.y += f.y;
        }
    }
    for (; j + 2 <= cnt; j += 2) {
        int     e = lst[j + hsel];
        __half2 v = *reinterpret_cast<const __half2*>(
                        g_contrib16 + (size_t)e * C + ch2 * 2);
        float2  f = __half22float2(v);
        acc.x += f.x;
        acc.y += f.y;
    }
    if (j < cnt && hsel == 0) {          // odd remainder: lanes 0-15 only
        int     e = lst[j];
        __half2 v = *reinterpret_cast<const __half2*>(
                        g_contrib16 + (size_t)e * C + ch2 * 2);
        float2  f = __half22float2(v);
        acc.x += f.x;
        acc.y += f.y;
    }
    // fold entry-B lanes into entry-A lanes
    acc.x += __shfl_down_sync(0xffffffffu, acc.x, 16);
    acc.y += __shfl_down_sync(0xffffffffu, acc.y, 16);
    if (hsel == 0)
        *reinterpret_cast<float2*>(out + (size_t)m * C + ch2 * 2) = acc;
}

// -------- 5. BN stats, stage 1: deterministic per-block partials ------------
__global__ __launch_bounds__(256) void k_bnpart(const float* __restrict__ out) {
    __shared__ float ss[8][32], sq[8][32];
    int ch = threadIdx.x & 31, w = threadIdx.x >> 5;
    int r0 = blockIdx.x * (NN / BN_BLKS);           // 128 rows per block
    float s = 0.f, q = 0.f;
    for (int r = r0 + w; r < r0 + (NN / BN_BLKS); r += 8) {
        float v = out[(size_t)r * C + ch];
        s += v;
        q += v * v;
    }
    ss[w][ch] = s;
    sq[w][ch] = q;
    __syncthreads();
    if (w == 0) {
        float S = 0.f, Q = 0.f;
#pragma unroll
        for (int t = 0; t < 8; ++t) { S += ss[t][ch]; Q += sq[t][ch]; }
        g_part[blockIdx.x * 64 + ch]      = S;
        g_part[blockIdx.x * 64 + 32 + ch] = Q;
    }
}

// -------- 6. BN stats, stage 2: final mean/var -> fused scale/shift ---------
__global__ __launch_bounds__(256) void k_bnfinal(const float* __restrict__ gamma,
                                                 const float* __restrict__ beta) {
    __shared__ float ss[8][32], sq[8][32];
    int ch = threadIdx.x & 31, w = threadIdx.x >> 5;
    float S = 0.f, Q = 0.f;
    for (int b = w; b < BN_BLKS; b += 8) {
        S += g_part[b * 64 + ch];
        Q += g_part[b * 64 + 32 + ch];
    }
    ss[w][ch] = S;
    sq[w][ch] = Q;
    __syncthreads();
    if (w == 0) {
        float St = 0.f, Qt = 0.f;
#pragma unroll
        for (int t = 0; t < 8; ++t) { St += ss[t][ch]; Qt += sq[t][ch]; }
        float mean  = St * (1.0f / NN);
        float var   = Qt * (1.0f / NN) - mean * mean;
        float rstd  = rsqrtf(var + EPS_F);
        float scale = gamma[ch] * rstd;
        g_stats[ch]      = scale;
        g_stats[32 + ch] = beta[ch] - mean * scale;
    }
}

// -------- 7. apply BN + ReLU in place --------
__global__ __launch_bounds__(256) void k_apply(float* __restrict__ out) {
    int i = blockIdx.x * blockDim.x + threadIdx.x;
    if (i >= NN * C) return;
    int   ch = i & 31;
    float y  = fmaf(out[i], g_stats[ch], g_stats[32 + ch]);
    out[i] = fmaxf(y, 0.f);
}

extern "C" void kernel_launch(void* const* d_in, const int* in_sizes, int n_in,
                              void* d_out, int out_size) {
    const float* data   = (const float*)d_in[0];   // [N, 32]
    const float* weight = (const float*)d_in[1];   // [27, 32, 32]
    const float* gamma  = (const float*)d_in[2];   // [32]
    const float* beta   = (const float*)d_in[3];   // [32]
    const int*   neigh  = (const int*)d_in[4];     // [N, 27]
    float*       out    = (float*)d_out;           // [N, 32]

    k_zero<<<(NN + 255) / 256, 256>>>();
    k_fill<<<(NKTOT / 4 + 255) / 256, 256>>>(neigh);
    k_gemm<<<dim3(NN / 256, 3), 256>>>(data, weight);
    k_gather<<<(NN * 32 + 255) / 256, 256>>>(out);
    k_bnpart<<<BN_BLKS, 256>>>(out);
    k_bnfinal<<<1, 256>>>(gamma, beta);
    k_apply<<<(NN * C + 255) / 256, 256>>>(out);
}

// round 3
// speedup vs baseline: 1.7125x; 1.4716x over previous
#include <cuda_runtime.h>
#include <cuda_fp16.h>

#define NN      131072
#define KK      27
#define C       32
#define NCOL    (KK * C)           // 864 output columns of the fused GEMM
#define NKTOT   (NN * KK)          // 3538944 scatter entries
#define CAP     96                 // bucket capacity (Poisson(27), P(overflow) ~ 2.5e-10)
#define BN_BLKS 1024
#define EPS_F   1e-5f

// -------- device scratch --------
__device__ __half g_contrib16[(size_t)NKTOT * C];  // 226 MB: contrib[n][k][o] fp16
__device__ int    g_fill[NN];
__device__ int    g_list[(size_t)NN * CAP];        // 50 MB inverse index
__device__ float  g_part[BN_BLKS * 64];
__device__ float  g_stats[64];
__device__ __align__(16) unsigned g_bfrag[108 * 2 * 32 * 2];  // 55 KB: B in mma frag order

__device__ __forceinline__ unsigned smem_u32(const void* p) {
    unsigned a;
    asm("{ .reg .u64 t; cvta.to.shared.u64 t, %1; cvt.u32.u64 %0, t; }" : "=r"(a) : "l"(p));
    return a;
}

// -------- 1. zero fill counters --------
__global__ void k_zero() {
    int i = blockIdx.x * blockDim.x + threadIdx.x;
    if (i < NN) g_fill[i] = 0;
}

// -------- 2. build inverse index --------
__global__ void k_fill(const int* __restrict__ neigh) {
    int t = blockIdx.x * blockDim.x + threadIdx.x;
    if (t >= NKTOT / 4) return;
    int4 m4 = reinterpret_cast<const int4*>(neigh)[t];
    int e0 = t * 4;
#pragma unroll
    for (int q = 0; q < 4; ++q) {
        int m   = (q == 0) ? m4.x : (q == 1) ? m4.y : (q == 2) ? m4.z : m4.w;
        int pos = atomicAdd(&g_fill[m], 1);
        if (pos < CAP) g_list[(size_t)m * CAP + pos] = e0 + q;
    }
}

// -------- 2b. pre-swizzle B into mma.m16n8k16 fragment order --------
// Bfrag[nt][s][lane][reg]: lane l, n = nt*8 + (l>>2), k0 = s*16 + (l&3)*2 + reg*8,
// value half2( B[k0][n], B[k0+1][n] ) with B[i][j] = weight[j/32][i][j%32].
__global__ void k_prep(const float* __restrict__ weight) {
    int idx = blockIdx.x * blockDim.x + threadIdx.x;
    if (idx >= 108 * 2 * 32 * 2) return;
    int reg = idx & 1, l = (idx >> 1) & 31, s = (idx >> 6) & 1, nt = idx >> 7;
    int k0 = s * 16 + (l & 3) * 2 + reg * 8;
    int n  = nt * 8 + (l >> 2);
    int jk = n >> 5, o = n & 31;
    float lo = weight[(jk * 32 + k0) * 32 + o];
    float hi = weight[(jk * 32 + k0 + 1) * 32 + o];
    __half2 h = __floats2half2_rn(lo, hi);
    g_bfrag[idx] = *reinterpret_cast<unsigned*>(&h);
}

// -------- 3. tensor-core GEMM: contrib[N x 864] = data[N x 32] @ B[32 x 864] --
// grid 1024 CTAs x 256 thr (8 warps). CTA = 128 rows, all 864 cols.
// A tile fp16 in smem (pad 40 halves: conflict-free ldmatrix), A-frags held in
// regs for the whole sweep. B frags streamed per 6-n-tile chunk (3 KB) from the
// pre-swizzled table. D staged in smem -> uint4 global stores (full sectors).
__global__ __launch_bounds__(256) void k_gemm(const float* __restrict__ data) {
    __shared__ __align__(16) __half    Ah[128][40];
    __shared__ __align__(16) unsigned  sB[6 * 128];          // one chunk of B frags
    __shared__ __align__(16) __half    Dst[8][16][56];       // per-warp stage, padded
    const int tid = threadIdx.x, lane = tid & 31, warp = tid >> 5;

    // load + convert A tile [128 x 32] fp32 -> fp16
    const float4* src = reinterpret_cast<const float4*>(data + (size_t)blockIdx.x * 128 * C);
#pragma unroll
    for (int t0 = 0; t0 < 4; ++t0) {
        int    t = tid + t0 * 256;
        float4 v = src[t];
        int r = t >> 3, c = (t & 7) * 4;
        *reinterpret_cast<__half2*>(&Ah[r][c])     = __floats2half2_rn(v.x, v.y);
        *reinterpret_cast<__half2*>(&Ah[r][c + 2]) = __floats2half2_rn(v.z, v.w);
    }
    __syncthreads();

    // A fragments via ldmatrix.x4: kstep0 = cols 0-15, kstep1 = cols 16-31
    unsigned a0[4], a1[4];
    {
        unsigned base = smem_u32(&Ah[warp * 16 + (lane & 15)][(lane >> 4) * 8]);
        asm volatile("ldmatrix.sync.aligned.m8n8.x4.shared.b16 {%0,%1,%2,%3}, [%4];"
                     : "=r"(a0[0]), "=r"(a0[1]), "=r"(a0[2]), "=r"(a0[3]) : "r"(base));
        asm volatile("ldmatrix.sync.aligned.m8n8.x4.shared.b16 {%0,%1,%2,%3}, [%4];"
                     : "=r"(a1[0]), "=r"(a1[1]), "=r"(a1[2]), "=r"(a1[3]) : "r"(base + 32));
    }

    const int r0 = lane >> 2;
    const int cc = (lane & 3) * 2;

    for (int chunk = 0; chunk < 18; ++chunk) {
        __syncthreads();
        if (tid < 192)
            reinterpret_cast<uint4*>(sB)[tid] =
                reinterpret_cast<const uint4*>(g_bfrag)[chunk * 192 + tid];
        __syncthreads();

#pragma unroll
        for (int t = 0; t < 6; ++t) {
            const unsigned* bp = sB + t * 128 + lane * 2;
            float d0 = 0.f, d1 = 0.f, d2 = 0.f, d3 = 0.f;
            asm volatile(
                "mma.sync.aligned.m16n8k16.row.col.f32.f16.f16.f32 "
                "{%0,%1,%2,%3}, {%4,%5,%6,%7}, {%8,%9}, {%0,%1,%2,%3};"
                : "+f"(d0), "+f"(d1), "+f"(d2), "+f"(d3)
                : "r"(a0[0]), "r"(a0[1]), "r"(a0[2]), "r"(a0[3]), "r"(bp[0]), "r"(bp[1]));
            asm volatile(
                "mma.sync.aligned.m16n8k16.row.col.f32.f16.f16.f32 "
                "{%0,%1,%2,%3}, {%4,%5,%6,%7}, {%8,%9}, {%0,%1,%2,%3};"
                : "+f"(d0), "+f"(d1), "+f"(d2), "+f"(d3)
                : "r"(a1[0]), "r"(a1[1]), "r"(a1[2]), "r"(a1[3]), "r"(bp[64]), "r"(bp[65]));
            *reinterpret_cast<__half2*>(&Dst[warp][r0][cc + t * 8]) =
                __floats2half2_rn(d0, d1);
            *reinterpret_cast<__half2*>(&Dst[warp][r0 + 8][cc + t * 8]) =
                __floats2half2_rn(d2, d3);
        }
        __syncwarp();
        // copy 16 rows x 48 cols (6 uint4 per row) to global — 96B/row contiguous
#pragma unroll
        for (int it = 0; it < 3; ++it) {
            int idx = it * 32 + lane;
            int r = idx / 6, c6 = idx % 6;
            uint4  v = *reinterpret_cast<const uint4*>(&Dst[warp][r][c6 * 8]);
            size_t n = (size_t)blockIdx.x * 128 + warp * 16 + r;
            *reinterpret_cast<uint4*>(g_contrib16 + n * NCOL + chunk * 48 + c6 * 8) = v;
        }
        __syncwarp();
    }
}

// -------- 4. gather: out[m][o] = sum over bucket of contrib16[e][o] --------
__global__ __launch_bounds__(256) void k_gather(float* __restrict__ out) {
    int m = (blockIdx.x * blockDim.x + threadIdx.x) >> 5;
    if (m >= NN) return;
    const int lane = threadIdx.x & 31;
    const int hsel = lane >> 4;
    const int ch2  = lane & 15;
    int cnt = g_fill[m];
    if (cnt > CAP) cnt = CAP;
    const int* lst = g_list + (size_t)m * CAP;

    float2 acc = make_float2(0.f, 0.f);
    int j = 0;
    for (; j + 8 <= cnt; j += 8) {
#pragma unroll
        for (int t = 0; t < 4; ++t) {
            int     e = lst[j + 2 * t + hsel];
            __half2 v = *reinterpret_cast<const __half2*>(
                            g_contrib16 + (size_t)e * C + ch2 * 2);
            float2  f = __half22float2(v);
            acc.x += f.x;
            acc.y += f.y;
        }
    }
    for (; j + 2 <= cnt; j += 2) {
        int     e = lst[j + hsel];
        __half2 v = *reinterpret_cast<const __half2*>(
                        g_contrib16 + (size_t)e * C + ch2 * 2);
        float2  f = __half22float2(v);
        acc.x += f.x;
        acc.y += f.y;
    }
    if (j < cnt && hsel == 0) {
        int     e = lst[j];
        __half2 v = *reinterpret_cast<const __half2*>(
                        g_contrib16 + (size_t)e * C + ch2 * 2);
        float2  f = __half22float2(v);
        acc.x += f.x;
        acc.y += f.y;
    }
    acc.x += __shfl_down_sync(0xffffffffu, acc.x, 16);
    acc.y += __shfl_down_sync(0xffffffffu, acc.y, 16);
    if (hsel == 0)
        *reinterpret_cast<float2*>(out + (size_t)m * C + ch2 * 2) = acc;
}

// -------- 5. BN stats, stage 1 --------
__global__ __launch_bounds__(256) void k_bnpart(const float* __restrict__ out) {
    __shared__ float ss[8][32], sq[8][32];
    int ch = threadIdx.x & 31, w = threadIdx.x >> 5;
    int r0 = blockIdx.x * (NN / BN_BLKS);
    float s = 0.f, q = 0.f;
    for (int r = r0 + w; r < r0 + (NN / BN_BLKS); r += 8) {
        float v = out[(size_t)r * C + ch];
        s += v;
        q += v * v;
    }
    ss[w][ch] = s;
    sq[w][ch] = q;
    __syncthreads();
    if (w == 0) {
        float S = 0.f, Q = 0.f;
#pragma unroll
        for (int t = 0; t < 8; ++t) { S += ss[t][ch]; Q += sq[t][ch]; }
        g_part[blockIdx.x * 64 + ch]      = S;
        g_part[blockIdx.x * 64 + 32 + ch] = Q;
    }
}

// -------- 6. BN stats, stage 2 --------
__global__ __launch_bounds__(256) void k_bnfinal(const float* __restrict__ gamma,
                                                 const float* __restrict__ beta) {
    __shared__ float ss[8][32], sq[8][32];
    int ch = threadIdx.x & 31, w = threadIdx.x >> 5;
    float S = 0.f, Q = 0.f;
    for (int b = w; b < BN_BLKS; b += 8) {
        S += g_part[b * 64 + ch];
        Q += g_part[b * 64 + 32 + ch];
    }
    ss[w][ch] = S;
    sq[w][ch] = Q;
    __syncthreads();
    if (w == 0) {
        float St = 0.f, Qt = 0.f;
#pragma unroll
        for (int t = 0; t < 8; ++t) { St += ss[t][ch]; Qt += sq[t][ch]; }
        float mean  = St * (1.0f / NN);
        float var   = Qt * (1.0f / NN) - mean * mean;
        float rstd  = rsqrtf(var + EPS_F);
        float scale = gamma[ch] * rstd;
        g_stats[ch]      = scale;
        g_stats[32 + ch] = beta[ch] - mean * scale;
    }
}

// -------- 7. apply BN + ReLU --------
__global__ __launch_bounds__(256) void k_apply(float* __restrict__ out) {
    int i = blockIdx.x * blockDim.x + threadIdx.x;
    if (i >= NN * C) return;
    int   ch = i & 31;
    float y  = fmaf(out[i], g_stats[ch], g_stats[32 + ch]);
    out[i] = fmaxf(y, 0.f);
}

extern "C" void kernel_launch(void* const* d_in, const int* in_sizes, int n_in,
                              void* d_out, int out_size) {
    const float* data   = (const float*)d_in[0];
    const float* weight = (const float*)d_in[1];
    const float* gamma  = (const float*)d_in[2];
    const float* beta   = (const float*)d_in[3];
    const int*   neigh  = (const int*)d_in[4];
    float*       out    = (float*)d_out;

    k_zero<<<(NN + 255) / 256, 256>>>();
    k_prep<<<(108 * 2 * 32 * 2 + 255) / 256, 256>>>(weight);
    k_fill<<<(NKTOT / 4 + 255) / 256, 256>>>(neigh);
    k_gemm<<<NN / 128, 256>>>(data);
    k_gather<<<(NN * 32 + 255) / 256, 256>>>(out);
    k_bnpart<<<BN_BLKS, 256>>>(out);
    k_bnfinal<<<1, 256>>>(gamma, beta);
    k_apply<<<(NN * C + 255) / 256, 256>>>(out);
}

// round 4
// speedup vs baseline: 2.1193x; 1.2375x over previous
#include <cuda_runtime.h>
#include <cuda_fp16.h>

#define NN      131072
#define KK      27
#define C       32
#define NCOL    (KK * C)           // 864 contrib columns
#define NKTOT   (NN * KK)          // 3538944 scatter entries
#define CAP     96                 // bucket capacity (Poisson(27), P(overflow) ~ 2.5e-10)
#define BN_BLKS 1024
#define EPS_F   1e-5f
#define GEMM_BLKS 1024             // NN/128
#define FILL_BLKS (NKTOT / 4 / 256)

// -------- device scratch --------
__device__ __align__(16) __half g_contrib16[(size_t)NKTOT * C];  // 226 MB
__device__ int    g_fill[NN];
__device__ __align__(16) int g_list[(size_t)NN * CAP];           // 50 MB inverse index
__device__ float  g_part[BN_BLKS * 64];
__device__ float  g_stats[64];
__device__ __align__(16) unsigned g_bfrag[108 * 2 * 32 * 2];     // 55 KB: B in frag order

__device__ __forceinline__ unsigned smem_u32(const void* p) {
    unsigned a;
    asm("{ .reg .u64 t; cvta.to.shared.u64 t, %1; cvt.u32.u64 %0, t; }" : "=r"(a) : "l"(p));
    return a;
}

// -------- 1. init: zero fill counters + pre-swizzle B into mma frag order ----
// Bfrag[nt][s][lane][reg]: k0 = s*16 + (l&3)*2 + reg*8, n = nt*8 + (l>>2),
// value half2( B[k0][n], B[k0+1][n] ), B[i][j] = weight[j/32][i][j%32].
__global__ void k_init(const float* __restrict__ weight) {
    int i = blockIdx.x * blockDim.x + threadIdx.x;
    if (i < NN) g_fill[i] = 0;
    if (i < 108 * 2 * 32 * 2) {
        int reg = i & 1, l = (i >> 1) & 31, s = (i >> 6) & 1, nt = i >> 7;
        int k0 = s * 16 + (l & 3) * 2 + reg * 8;
        int n  = nt * 8 + (l >> 2);
        int jk = n >> 5, o = n & 31;
        float lo = weight[(jk * 32 + k0) * 32 + o];
        float hi = weight[(jk * 32 + k0 + 1) * 32 + o];
        __half2 h = __floats2half2_rn(lo, hi);
        g_bfrag[i] = *reinterpret_cast<unsigned*>(&h);
    }
}

// -------- 2. merged work kernel: GEMM (blocks 0..1023) + fill (rest) --------
// GEMM: contrib[N x 864] = data[N x 32] @ B[32 x 864] on tensor cores.
// CTA = 128 rows. A-frags in regs (ldmatrix from padded smem, once). B-frags
// LDG.64 from L1-resident g_bfrag. Epilogue: columns within each 32-wide
// k-block permuted so a lane's 4 half2 are contiguous -> one STG.128 per lane
// per row; warp store = 8 rows x 64B contiguous (100% sectors), zero smem.
// Column perm: pos p in [0,32): p = j*8 + t*2 + b  <->  channel o = t*8+j*2+b.
__global__ __launch_bounds__(256) void k_work(const float* __restrict__ data,
                                              const int* __restrict__ neigh) {
    __shared__ __align__(16) __half Ah[128][40];
    const int tid = threadIdx.x, lane = tid & 31, warp = tid >> 5;

    if (blockIdx.x >= GEMM_BLKS) {
        // ---- fill: build inverse index ----
        int t = (blockIdx.x - GEMM_BLKS) * 256 + tid;
        int4 m4 = __ldcs(reinterpret_cast<const int4*>(neigh) + t);
        int e0 = t * 4;
#pragma unroll
        for (int q = 0; q < 4; ++q) {
            int m   = (q == 0) ? m4.x : (q == 1) ? m4.y : (q == 2) ? m4.z : m4.w;
            int pos = atomicAdd(&g_fill[m], 1);
            if (pos < CAP) __stcs(&g_list[(size_t)m * CAP + pos], e0 + q);
        }
        return;
    }

    // ---- GEMM ----
    const int bid = blockIdx.x;
    const float4* src = reinterpret_cast<const float4*>(data + (size_t)bid * 128 * C);
#pragma unroll
    for (int t0 = 0; t0 < 4; ++t0) {
        int    t = tid + t0 * 256;
        float4 v = src[t];
        int r = t >> 3, c = (t & 7) * 4;
        *reinterpret_cast<__half2*>(&Ah[r][c])     = __floats2half2_rn(v.x, v.y);
        *reinterpret_cast<__half2*>(&Ah[r][c + 2]) = __floats2half2_rn(v.z, v.w);
    }
    __syncthreads();

    unsigned a0[4], a1[4];
    {
        unsigned base = smem_u32(&Ah[warp * 16 + (lane & 15)][(lane >> 4) * 8]);
        asm volatile("ldmatrix.sync.aligned.m8n8.x4.shared.b16 {%0,%1,%2,%3}, [%4];"
                     : "=r"(a0[0]), "=r"(a0[1]), "=r"(a0[2]), "=r"(a0[3]) : "r"(base));
        asm volatile("ldmatrix.sync.aligned.m8n8.x4.shared.b16 {%0,%1,%2,%3}, [%4];"
                     : "=r"(a1[0]), "=r"(a1[1]), "=r"(a1[2]), "=r"(a1[3]) : "r"(base + 32));
    }

    const int r0 = lane >> 2;
    const int j  = lane & 3;
    const size_t nlo = (size_t)bid * 128 + warp * 16 + r0;
    __half* plo = g_contrib16 + nlo * NCOL + j * 8;
    __half* phi = plo + (size_t)8 * NCOL;

    const uint2* bf = reinterpret_cast<const uint2*>(g_bfrag) + lane;

    for (int kb = 0; kb < 27; ++kb) {
        uint2 b[8];                               // [t*2+s], stride 32 uint2
#pragma unroll
        for (int q = 0; q < 8; ++q) b[q] = bf[(kb * 8 + q) * 32];

        unsigned hlo[4], hhi[4];
#pragma unroll
        for (int t = 0; t < 4; ++t) {
            float d0 = 0.f, d1 = 0.f, d2 = 0.f, d3 = 0.f;
            asm volatile(
                "mma.sync.aligned.m16n8k16.row.col.f32.f16.f16.f32 "
                "{%0,%1,%2,%3}, {%4,%5,%6,%7}, {%8,%9}, {%0,%1,%2,%3};"
                : "+f"(d0), "+f"(d1), "+f"(d2), "+f"(d3)
                : "r"(a0[0]), "r"(a0[1]), "r"(a0[2]), "r"(a0[3]),
                  "r"(b[t * 2].x), "r"(b[t * 2].y));
            asm volatile(
                "mma.sync.aligned.m16n8k16.row.col.f32.f16.f16.f32 "
                "{%0,%1,%2,%3}, {%4,%5,%6,%7}, {%8,%9}, {%0,%1,%2,%3};"
                : "+f"(d0), "+f"(d1), "+f"(d2), "+f"(d3)
                : "r"(a1[0]), "r"(a1[1]), "r"(a1[2]), "r"(a1[3]),
                  "r"(b[t * 2 + 1].x), "r"(b[t * 2 + 1].y));
            __half2 l2 = __floats2half2_rn(d0, d1);
            __half2 h2 = __floats2half2_rn(d2, d3);
            hlo[t] = *reinterpret_cast<unsigned*>(&l2);
            hhi[t] = *reinterpret_cast<unsigned*>(&h2);
        }
        uint4 vlo = make_uint4(hlo[0], hlo[1], hlo[2], hlo[3]);
        uint4 vhi = make_uint4(hhi[0], hhi[1], hhi[2], hhi[3]);
        __stcs(reinterpret_cast<uint4*>(plo + kb * 32), vlo);
        __stcs(reinterpret_cast<uint4*>(phi + kb * 32), vhi);
    }
}

// -------- 3. gather: out[m][perm] = sum over bucket of contrib16[e][:] ------
// one warp per node; lanes 0-15 handle entry A of each pair, 16-31 entry B;
// half2 index p2 -> output channels ( (p2&3)*8 + (p2>>2)*2 , +1 ) per the
// GEMM column permutation.
__global__ __launch_bounds__(256) void k_gather(float* __restrict__ out) {
    int m = (blockIdx.x * blockDim.x + threadIdx.x) >> 5;
    if (m >= NN) return;
    const int lane = threadIdx.x & 31;
    const int hsel = lane >> 4;
    const int ch2  = lane & 15;
    int cnt = g_fill[m];
    if (cnt > CAP) cnt = CAP;
    const int* lst = g_list + (size_t)m * CAP;

    float2 acc = make_float2(0.f, 0.f);
    int j = 0;
    for (; j + 16 <= cnt; j += 16) {
        __half2 v[8];
#pragma unroll
        for (int t = 0; t < 8; ++t) {
            int e = lst[j + 2 * t + hsel];
            v[t]  = __ldcs(reinterpret_cast<const __half2*>(
                        g_contrib16 + (size_t)e * C + ch2 * 2));
        }
#pragma unroll
        for (int t = 0; t < 8; ++t) {
            float2 f = __half22float2(v[t]);
            acc.x += f.x; acc.y += f.y;
        }
    }
    for (; j + 2 <= cnt; j += 2) {
        int     e = lst[j + hsel];
        __half2 v = __ldcs(reinterpret_cast<const __half2*>(
                        g_contrib16 + (size_t)e * C + ch2 * 2));
        float2  f = __half22float2(v);
        acc.x += f.x; acc.y += f.y;
    }
    if (j < cnt && hsel == 0) {
        int     e = lst[j];
        __half2 v = __ldcs(reinterpret_cast<const __half2*>(
                        g_contrib16 + (size_t)e * C + ch2 * 2));
        float2  f = __half22float2(v);
        acc.x += f.x; acc.y += f.y;
    }
    acc.x += __shfl_down_sync(0xffffffffu, acc.x, 16);
    acc.y += __shfl_down_sync(0xffffffffu, acc.y, 16);
    if (hsel == 0) {
        int co = (ch2 & 3) * 8 + (ch2 >> 2) * 2;   // undo column permutation
        *reinterpret_cast<float2*>(out + (size_t)m * C + co) = acc;
    }
}

// -------- 4. BN stats, stage 1 --------
__global__ __launch_bounds__(256) void k_bnpart(const float* __restrict__ out) {
    __shared__ float ss[8][32], sq[8][32];
    int ch = threadIdx.x & 31, w = threadIdx.x >> 5;
    int r0 = blockIdx.x * (NN / BN_BLKS);
    float s = 0.f, q = 0.f;
    for (int r = r0 + w; r < r0 + (NN / BN_BLKS); r += 8) {
        float v = out[(size_t)r * C + ch];
        s += v;
        q += v * v;
    }
    ss[w][ch] = s;
    sq[w][ch] = q;
    __syncthreads();
    if (w == 0) {
        float S = 0.f, Q = 0.f;
#pragma unroll
        for (int t = 0; t < 8; ++t) { S += ss[t][ch]; Q += sq[t][ch]; }
        g_part[blockIdx.x * 64 + ch]      = S;
        g_part[blockIdx.x * 64 + 32 + ch] = Q;
    }
}

// -------- 5. BN stats, stage 2 --------
__global__ __launch_bounds__(256) void k_bnfinal(const float* __restrict__ gamma,
                                                 const float* __restrict__ beta) {
    __shared__ float ss[8][32], sq[8][32];
    int ch = threadIdx.x & 31, w = threadIdx.x >> 5;
    float S = 0.f, Q = 0.f;
    for (int b = w; b < BN_BLKS; b += 8) {
        S += g_part[b * 64 + ch];
        Q += g_part[b * 64 + 32 + ch];
    }
    ss[w][ch] = S;
    sq[w][ch] = Q;
    __syncthreads();
    if (w == 0) {
        float St = 0.f, Qt = 0.f;
#pragma unroll
        for (int t = 0; t < 8; ++t) { St += ss[t][ch]; Qt += sq[t][ch]; }
        float mean  = St * (1.0f / NN);
        float var   = Qt * (1.0f / NN) - mean * mean;
        float rstd  = rsqrtf(var + EPS_F);
        float scale = gamma[ch] * rstd;
        g_stats[ch]      = scale;
        g_stats[32 + ch] = beta[ch] - mean * scale;
    }
}

// -------- 6. apply BN + ReLU --------
__global__ __launch_bounds__(256) void k_apply(float* __restrict__ out) {
    int i = blockIdx.x * blockDim.x + threadIdx.x;
    if (i >= NN * C) return;
    int   ch = i & 31;
    float y  = fmaf(out[i], g_stats[ch], g_stats[32 + ch]);
    out[i] = fmaxf(y, 0.f);
}

extern "C" void kernel_launch(void* const* d_in, const int* in_sizes, int n_in,
                              void* d_out, int out_size) {
    const float* data   = (const float*)d_in[0];
    const float* weight = (const float*)d_in[1];
    const float* gamma  = (const float*)d_in[2];
    const float* beta   = (const float*)d_in[3];
    const int*   neigh  = (const int*)d_in[4];
    float*       out    = (float*)d_out;

    k_init<<<NN / 256, 256>>>(weight);
    k_work<<<GEMM_BLKS + FILL_BLKS, 256>>>(data, neigh);
    k_gather<<<(NN * 32 + 255) / 256, 256>>>(out);
    k_bnpart<<<BN_BLKS, 256>>>(out);
    k_bnfinal<<<1, 256>>>(gamma, beta);
    k_apply<<<(NN * C + 255) / 256, 256>>>(out);
}